// round 10
// baseline (speedup 1.0000x reference)
#include <cuda_runtime.h>
#include <cuda_bf16.h>
#include <cstdint>

#define BB  2
#define NN  1024
#define KK  48
#define HH  128
#define FFD 512
#define BN  (BB*NN)
#define NEDGE (BN*KK)          // 98304
#define MT  128
#define NCTA (NEDGE/MT)        // 768
#define NTHR 512

// smem: tiles are 128x64 bf16 = 16KB, 128B rows (SW128)
#define TILE_B  16384
#define SM_B    1024
#define SM_A2   (SM_B  + 4*TILE_B)
#define SM_A3   (SM_A2 + 4*TILE_B)
#define SM_TOTAL (SM_A3 + 4*TILE_B)        // 197632

#define WOFF_G1 0
#define WOFF_G2 (384*HH)
#define WOFF_G3 (WOFF_G2 + 128*HH)
#define WMSG    (WOFF_G3 + 128*HH)

__device__ float g_hV1[BN*HH];
__device__ float g_m[(size_t)NEDGE*HH];
__device__ float g_cw[BN*HH];
__device__ __align__(16) __nv_bfloat16 g_WThi[2*WMSG];
__device__ __align__(16) __nv_bfloat16 g_WTlo[2*WMSG];
__device__ __align__(16) __nv_bfloat16 g_hVhi[BN*HH],  g_hVlo[BN*HH];
__device__ __align__(16) __nv_bfloat16 g_hV2hi[BN*HH], g_hV2lo[BN*HH];
__device__ int g_idx64;

__device__ __forceinline__ float gelu_exact(float x) {
    return 0.5f * x * (1.0f + erff(x * 0.70710678118654752f));
}

__global__ void detect_idx_kernel(const int* __restrict__ e32) {
    int all0 = 1;
    #pragma unroll
    for (int i = 1; i < 96; i += 2) all0 &= (e32[i] == 0);
    g_idx64 = all0;
}

__device__ __forceinline__ int load_nbidx(const void* Eidx, int is64, long long pos) {
    int v;
    if (is64) v = (int)((const long long*)Eidx)[pos];
    else      v = ((const int*)Eidx)[pos];
    v = v < 0 ? 0 : (v >= NN ? NN - 1 : v);
    return v;
}

// -------- prep: 6 weight transposes + hV split --------
#define PW_BLKS 640
#define PV_BLKS 256
__global__ void __launch_bounds__(256)
prep_all(const float* __restrict__ W1,  const float* __restrict__ W2,
         const float* __restrict__ W3,  const float* __restrict__ W11,
         const float* __restrict__ W12, const float* __restrict__ W13,
         const float* __restrict__ hV)
{
    int blk = blockIdx.x, tid = threadIdx.x;
    if (blk < PW_BLKS) {
        int id = blk * 256 + tid;
        const float* src; int base, K;
        if      (id < 49152)  { src = W1;  base = 0;      K = 384; }
        else if (id < 65536)  { src = W2;  base = 49152;  K = 128; }
        else if (id < 81920)  { src = W3;  base = 65536;  K = 128; }
        else if (id < 131072) { src = W11; base = 81920;  K = 384; }
        else if (id < 147456) { src = W12; base = 131072; K = 128; }
        else                  { src = W13; base = 147456; K = 128; }
        int local = id - base;
        int k = local >> 7, n = local & 127;
        float x = src[local];
        __nv_bfloat16 h = __float2bfloat16(x);
        g_WThi[base + (size_t)n * K + k] = h;
        g_WTlo[base + (size_t)n * K + k] = __float2bfloat16(x - __bfloat162float(h));
    } else {
        int idx = (blk - PW_BLKS) * 256 + tid;
        float4 v = ((const float4*)hV)[idx];
        __nv_bfloat16 h0 = __float2bfloat16(v.x), h1 = __float2bfloat16(v.y);
        __nv_bfloat16 h2 = __float2bfloat16(v.z), h3 = __float2bfloat16(v.w);
        __nv_bfloat162* ph = (__nv_bfloat162*)(g_hVhi + (size_t)idx * 4);
        __nv_bfloat162* pl = (__nv_bfloat162*)(g_hVlo + (size_t)idx * 4);
        ph[0] = __nv_bfloat162(h0, h1); ph[1] = __nv_bfloat162(h2, h3);
        pl[0] = __nv_bfloat162(__float2bfloat16(v.x - __bfloat162float(h0)),
                               __float2bfloat16(v.y - __bfloat162float(h1)));
        pl[1] = __nv_bfloat162(__float2bfloat16(v.z - __bfloat162float(h2)),
                               __float2bfloat16(v.w - __bfloat162float(h3)));
    }
}

// -------- cw: g_cw[bn][j] = bias[j] + center . Wtop[:,j] --------
__global__ void __launch_bounds__(128)
cw_kernel(const float* __restrict__ center, const float* __restrict__ Wtop,
          const float* __restrict__ bias)
{
    __shared__ float sc[128];
    int bn = blockIdx.x, j = threadIdx.x;
    sc[j] = center[(size_t)bn * HH + j];
    __syncthreads();
    float acc = bias[j];
    #pragma unroll 8
    for (int i = 0; i < 128; i++) acc = fmaf(sc[i], Wtop[i * HH + j], acc);
    g_cw[(size_t)bn * HH + j] = acc;
}

// ---------------- PTX helpers ----------------
__device__ __forceinline__ uint32_t smem_u32(const void* p) {
    uint32_t a;
    asm("{ .reg .u64 t; cvta.to.shared.u64 t, %1; cvt.u32.u64 %0, t; }" : "=r"(a) : "l"(p));
    return a;
}
__device__ __forceinline__ uint32_t sw128(uint32_t off) {
    return off ^ ((off >> 3) & 0x70);
}
__device__ __forceinline__ void ldsm4(uint32_t* r, uint32_t addr) {
    asm volatile("ldmatrix.sync.aligned.m8n8.x4.shared.b16 {%0,%1,%2,%3}, [%4];"
        : "=r"(r[0]), "=r"(r[1]), "=r"(r[2]), "=r"(r[3]) : "r"(addr));
}
__device__ __forceinline__ void mma16816(float* d, const uint32_t* a, const uint32_t* b) {
    asm volatile("mma.sync.aligned.m16n8k16.row.col.f32.bf16.bf16.f32 "
        "{%0,%1,%2,%3}, {%4,%5,%6,%7}, {%8,%9}, {%0,%1,%2,%3};"
        : "+f"(d[0]), "+f"(d[1]), "+f"(d[2]), "+f"(d[3])
        : "r"(a[0]), "r"(a[1]), "r"(a[2]), "r"(a[3]), "r"(b[0]), "r"(b[1]));
}
__device__ __forceinline__ void ldsmA(uint32_t* r, uint32_t tbase, int mrow, int klo, int lane) {
    int q = lane >> 3;
    int row = mrow + (lane & 7) + 8 * (q & 1);
    int kk  = klo + 8 * (q >> 1);
    ldsm4(r, tbase + sw128((uint32_t)(row * 128 + kk * 2)));
}
__device__ __forceinline__ void ldsmB(uint32_t* r, uint32_t tbase, int nrow0, int klo, int lane) {
    int q = lane >> 3;
    int row = nrow0 + (lane & 7) + 8 * (q >> 1);
    int kk  = klo + 8 * (q & 1);
    ldsm4(r, tbase + sw128((uint32_t)(row * 128 + kk * 2)));
}
__device__ __forceinline__ uint32_t pack_bf2(__nv_bfloat16 a, __nv_bfloat16 b) {
    return (uint32_t)__bfloat16_as_ushort(a) | ((uint32_t)__bfloat16_as_ushort(b) << 16);
}
__device__ __forceinline__ void split2(float x, float y, uint32_t& hi, uint32_t& lo) {
    __nv_bfloat16 hx = __float2bfloat16(x), hy = __float2bfloat16(y);
    __nv_bfloat16 lx = __float2bfloat16(x - __bfloat162float(hx));
    __nv_bfloat16 ly = __float2bfloat16(y - __bfloat162float(hy));
    hi = pack_bf2(hx, hy);
    lo = pack_bf2(lx, ly);
}

// ---------------- fused GEMM-chain message kernel ----------------
// 512 threads = 16 warps. Warp tile 64x32; warp pair (wid, wid+8) shares one
// tile and splits the 4 k16-steps of each chunk (kpar = wid>>3). Partials are
// combined through smem after each GEMM.
template<bool EDGE>
__global__ void __launch_bounds__(NTHR, 1)
gemm_msg_kernel(const __nv_bfloat16* __restrict__ vhi,
                const __nv_bfloat16* __restrict__ vlo,
                const float* __restrict__ hE,
                const void*  __restrict__ Eidx,
                const float* __restrict__ maskA,
                const float* __restrict__ bb, const float* __restrict__ bc,
                int wbase,
                const float* __restrict__ lng, const float* __restrict__ lnb,
                float* __restrict__ out)
{
    extern __shared__ uint8_t smem8[];
    const int tid  = threadIdx.x;
    const int wid  = tid >> 5;
    const int lane = tid & 31;
    const int e0   = blockIdx.x * MT;
    const int is64 = g_idx64;
    const uint32_t sbase = smem_u32(smem8);

    const int m0   = (wid & 1) * 64;          // 2 m-positions x 64 rows
    const int n0   = ((wid >> 1) & 3) * 32;   // 4 n-positions x 32 cols
    const int kpar = wid >> 3;                // 0/1: which k-half of each chunk

    const __nv_bfloat16* WTh = g_WThi + wbase;
    const __nv_bfloat16* WTl = g_WTlo + wbase;

    float acc[4][4][4];
    auto zero_acc = [&]() {
        #pragma unroll
        for (int mt = 0; mt < 4; mt++)
            #pragma unroll
            for (int nt = 0; nt < 4; nt++)
                #pragma unroll
                for (int i = 0; i < 4; i++) acc[mt][nt][i] = 0.f;
    };

    auto fill_B = [&](int woff, int Klen, int kbase, int slot) {
        const __nv_bfloat16* bh = WTh + woff;
        const __nv_bfloat16* bl = WTl + woff;
        int u = tid & 7;
        uint8_t* dh = smem8 + SM_B + slot * TILE_B;
        uint8_t* dl = smem8 + SM_B + (2 + slot) * TILE_B;
        #pragma unroll
        for (int n = tid >> 3; n < 128; n += 64) {
            uint4 vh = ((const uint4*)(bh + (size_t)n * Klen + kbase))[u];
            uint4 vl = ((const uint4*)(bl + (size_t)n * Klen + kbase))[u];
            uint32_t sw = sw128((uint32_t)n * 128 + u * 16);
            *(uint4*)(dh + sw) = vh;
            *(uint4*)(dl + sw) = vl;
        }
    };

    auto fill_A = [&](int ch, int buf) {
        uint8_t* aH = smem8 + SM_A3 + (2 * buf) * TILE_B;
        uint8_t* aL = smem8 + SM_A3 + (2 * buf + 1) * TILE_B;
        if (ch < 2) {
            int c4 = tid & 15;
            #pragma unroll
            for (int r = tid >> 4; r < MT; r += 32) {
                int e = e0 + r;
                const float* src = hE + (size_t)e * HH + ch * 64;
                float4 v = *((const float4*)src + c4);
                uint32_t h01, l01, h23, l23;
                split2(v.x, v.y, h01, l01);
                split2(v.z, v.w, h23, l23);
                uint32_t sw = sw128((uint32_t)r * 128 + c4 * 8);
                *(uint2*)(aH + sw) = make_uint2(h01, h23);
                *(uint2*)(aL + sw) = make_uint2(l01, l23);
            }
        } else {
            int u = tid & 7;
            #pragma unroll
            for (int r = tid >> 3; r < MT; r += 64) {
                int e = e0 + r;
                int b  = e / (KK * NN);
                int nb = load_nbidx(Eidx, is64, e);
                const __nv_bfloat16* sh = vhi + ((size_t)b * NN + nb) * HH + (ch - 2) * 64;
                const __nv_bfloat16* sl = vlo + ((size_t)b * NN + nb) * HH + (ch - 2) * 64;
                uint4 vh = ((const uint4*)sh)[u];
                uint4 vl = ((const uint4*)sl)[u];
                uint32_t sw = sw128((uint32_t)r * 128 + u * 16);
                *(uint4*)(aH + sw) = vh;
                *(uint4*)(aL + sw) = vl;
            }
        }
    };

    // half-chunk MMA: this warp handles ks in {kpar*2, kpar*2+1}
    auto mma_half = [&](uint32_t aHi, uint32_t aLo, uint32_t bHi, uint32_t bLo) {
        #pragma unroll
        for (int kq = 0; kq < 2; kq++) {
            int klo = (kpar * 2 + kq) * 16;
            uint32_t Ah[4][4], Al[4][4];
            #pragma unroll
            for (int mt = 0; mt < 4; mt++) {
                ldsmA(Ah[mt], aHi, m0 + 16 * mt, klo, lane);
                ldsmA(Al[mt], aLo, m0 + 16 * mt, klo, lane);
            }
            uint32_t Bh[2][4], Bl[2][4];
            #pragma unroll
            for (int p = 0; p < 2; p++) {
                ldsmB(Bh[p], bHi, n0 + p * 16, klo, lane);
                ldsmB(Bl[p], bLo, n0 + p * 16, klo, lane);
            }
            #pragma unroll
            for (int mt = 0; mt < 4; mt++) {
                #pragma unroll
                for (int p = 0; p < 2; p++) {
                    #pragma unroll
                    for (int s = 0; s < 2; s++) {
                        int nt = p * 2 + s;
                        mma16816(acc[mt][nt], Ah[mt], &Bh[p][s * 2]);
                        mma16816(acc[mt][nt], Ah[mt], &Bl[p][s * 2]);
                        mma16816(acc[mt][nt], Al[mt], &Bh[p][s * 2]);
                    }
                }
            }
        }
    };

    // combine kpar partials via the (momentarily dead) B region
    float* sRed = (float*)(smem8 + SM_B);
    auto combine = [&]() {
        if (kpar == 1) {
            #pragma unroll
            for (int mt = 0; mt < 4; mt++) {
                int row = m0 + mt * 16 + (lane >> 2);
                #pragma unroll
                for (int nt = 0; nt < 4; nt++) {
                    int c0 = n0 + nt * 8 + 2 * (lane & 3);
                    *(float2*)(sRed + row * 128 + c0)       = make_float2(acc[mt][nt][0], acc[mt][nt][1]);
                    *(float2*)(sRed + (row + 8) * 128 + c0) = make_float2(acc[mt][nt][2], acc[mt][nt][3]);
                }
            }
        }
        __syncthreads();
        if (kpar == 0) {
            #pragma unroll
            for (int mt = 0; mt < 4; mt++) {
                int row = m0 + mt * 16 + (lane >> 2);
                #pragma unroll
                for (int nt = 0; nt < 4; nt++) {
                    int c0 = n0 + nt * 8 + 2 * (lane & 3);
                    float2 p0 = *(float2*)(sRed + row * 128 + c0);
                    float2 p1 = *(float2*)(sRed + (row + 8) * 128 + c0);
                    acc[mt][nt][0] += p0.x; acc[mt][nt][1] += p0.y;
                    acc[mt][nt][2] += p1.x; acc[mt][nt][3] += p1.y;
                }
            }
        }
        __syncthreads();
    };

    auto epi_act = [&](const float* __restrict__ bias, bool useCW, uint32_t dstOff) {
        if (kpar != 0) return;   // only kpar=0 warps hold full sums
        #pragma unroll
        for (int mt = 0; mt < 4; mt++) {
            int row = m0 + mt * 16 + (lane >> 2);
            const float* cw0 = nullptr; const float* cw1 = nullptr;
            if (useCW) {
                cw0 = g_cw + (size_t)((e0 + row) / KK) * HH;
                cw1 = g_cw + (size_t)((e0 + row + 8) / KK) * HH;
            }
            #pragma unroll
            for (int nt = 0; nt < 4; nt++) {
                int c0 = n0 + nt * 8 + 2 * (lane & 3);
                float b00, b01, b10, b11;
                if (useCW) { b00 = cw0[c0]; b01 = cw0[c0 + 1]; b10 = cw1[c0]; b11 = cw1[c0 + 1]; }
                else       { b00 = b10 = bias[c0]; b01 = b11 = bias[c0 + 1]; }
                int kt = c0 >> 6, kk = c0 & 63;
                uint8_t* dH = smem8 + dstOff + kt * TILE_B;
                uint8_t* dL = smem8 + dstOff + (2 + kt) * TILE_B;
                float x0 = gelu_exact(acc[mt][nt][0] + b00);
                float y0 = gelu_exact(acc[mt][nt][1] + b01);
                float x1 = gelu_exact(acc[mt][nt][2] + b10);
                float y1 = gelu_exact(acc[mt][nt][3] + b11);
                uint32_t hi, lo;
                split2(x0, y0, hi, lo);
                uint32_t sw = sw128((uint32_t)(row * 128 + kk * 2));
                *(uint32_t*)(dH + sw) = hi; *(uint32_t*)(dL + sw) = lo;
                split2(x1, y1, hi, lo);
                sw = sw128((uint32_t)((row + 8) * 128 + kk * 2));
                *(uint32_t*)(dH + sw) = hi; *(uint32_t*)(dL + sw) = lo;
            }
        }
    };

    // ===== GEMM1: K=256, 4 chunks double-buffered; each warp does its k-half =====
    zero_acc();
    fill_A(0, 0);
    fill_B(WOFF_G1, 384, 128, 0);
    __syncthreads();
    #pragma unroll 1
    for (int ch = 0; ch < 4; ch++) {
        int bi = ch & 1;
        if (ch < 3) {
            fill_A(ch + 1, bi ^ 1);
            fill_B(WOFF_G1, 384, 128 + (ch + 1) * 64, bi ^ 1);
        }
        mma_half(sbase + SM_A3 + (2 * bi) * TILE_B,
                 sbase + SM_A3 + (2 * bi + 1) * TILE_B,
                 sbase + SM_B + bi * TILE_B,
                 sbase + SM_B + (2 + bi) * TILE_B);
        __syncthreads();
    }
    combine();
    epi_act(nullptr, true, SM_A2);
    fill_B(WOFF_G2, 128, 0, 0);
    fill_B(WOFF_G2, 128, 64, 1);
    zero_acc();
    __syncthreads();

    // ===== GEMM2 =====
    #pragma unroll
    for (int kt = 0; kt < 2; kt++)
        mma_half(sbase + SM_A2 + kt * TILE_B, sbase + SM_A2 + (2 + kt) * TILE_B,
                 sbase + SM_B  + kt * TILE_B, sbase + SM_B  + (2 + kt) * TILE_B);
    __syncthreads();
    combine();
    epi_act(bb, false, SM_A3);
    fill_B(WOFF_G3, 128, 0, 0);
    fill_B(WOFF_G3, 128, 64, 1);
    zero_acc();
    __syncthreads();

    // ===== GEMM3 =====
    #pragma unroll
    for (int kt = 0; kt < 2; kt++)
        mma_half(sbase + SM_A3 + kt * TILE_B, sbase + SM_A3 + (2 + kt) * TILE_B,
                 sbase + SM_B  + kt * TILE_B, sbase + SM_B  + (2 + kt) * TILE_B);
    __syncthreads();
    combine();

    float* sOut = (float*)(smem8 + SM_B);
    if (kpar == 0) {
        #pragma unroll
        for (int mt = 0; mt < 4; mt++) {
            int row = m0 + mt * 16 + (lane >> 2);
            float mk0 = 1.f, mk1 = 1.f;
            if (!EDGE) { mk0 = maskA[e0 + row]; mk1 = maskA[e0 + row + 8]; }
            #pragma unroll
            for (int nt = 0; nt < 4; nt++) {
                int c0 = n0 + nt * 8 + 2 * (lane & 3);
                float b0v = bc[c0], b1v = bc[c0 + 1];
                sOut[row * 128 + c0]           = (acc[mt][nt][0] + b0v) * mk0;
                sOut[row * 128 + c0 + 1]       = (acc[mt][nt][1] + b1v) * mk0;
                sOut[(row + 8) * 128 + c0]     = (acc[mt][nt][2] + b0v) * mk1;
                sOut[(row + 8) * 128 + c0 + 1] = (acc[mt][nt][3] + b1v) * mk1;
            }
        }
    }
    __syncthreads();

    if (!EDGE) {
        float4* d4 = (float4*)(g_m + (size_t)e0 * HH);
        const float4* s4 = (const float4*)sOut;
        #pragma unroll
        for (int p = 0; p < 8; p++) d4[tid + p * NTHR] = s4[tid + p * NTHR];
    } else {
        for (int r = wid; r < MT; r += 16) {
            const float* her = hE + (size_t)(e0 + r) * HH;
            float v[4];
            #pragma unroll
            for (int u = 0; u < 4; u++) {
                int c = lane + 32 * u;
                v[u] = sOut[r * 128 + c] + her[c];
            }
            float s  = v[0] + v[1] + v[2] + v[3];
            float ss = v[0]*v[0] + v[1]*v[1] + v[2]*v[2] + v[3]*v[3];
            #pragma unroll
            for (int o = 16; o; o >>= 1) {
                s  += __shfl_xor_sync(0xffffffffu, s, o);
                ss += __shfl_xor_sync(0xffffffffu, ss, o);
            }
            float mean = s * (1.0f / 128.0f);
            float rstd = rsqrtf(ss * (1.0f / 128.0f) - mean * mean + 1e-5f);
            #pragma unroll
            for (int u = 0; u < 4; u++) {
                int c = lane + 32 * u;
                out[(size_t)(e0 + r) * HH + c] = (v[u] - mean) * rstd * lng[c] + lnb[c];
            }
        }
    }
}

// ---------------- node reduction + LN1 ----------------
__global__ void __launch_bounds__(128)
reduce_ln1(const float* __restrict__ hV,
           const float* __restrict__ lng, const float* __restrict__ lnb)
{
    int bn = blockIdx.x, j = threadIdx.x;
    int w = j >> 5, lane = j & 31;
    float s = 0.f;
    const float* mp = g_m + (size_t)bn * KK * HH + j;
    #pragma unroll 8
    for (int k = 0; k < KK; k++) s += mp[(size_t)k * HH];
    float v = hV[(size_t)bn * HH + j] + s * (1.0f / 48.0f);

    __shared__ float rs[4], rq[4];
    float a = v, q = v * v;
    #pragma unroll
    for (int o = 16; o; o >>= 1) {
        a += __shfl_xor_sync(0xffffffffu, a, o);
        q += __shfl_xor_sync(0xffffffffu, q, o);
    }
    if (lane == 0) { rs[w] = a; rq[w] = q; }
    __syncthreads();
    float S = rs[0] + rs[1] + rs[2] + rs[3];
    float Q = rq[0] + rq[1] + rq[2] + rq[3];
    float mean = S * (1.0f / 128.0f);
    float rstd = rsqrtf(Q * (1.0f / 128.0f) - mean * mean + 1e-5f);
    g_hV1[(size_t)bn * HH + j] = (v - mean) * rstd * lng[j] + lnb[j];
}

// ---------------- FFN + LN2 + mask_V (+ bf16 split of h_Vn) ----------------
__global__ void __launch_bounds__(256, 1)
ffn_kernel(const float* __restrict__ Win, const float* __restrict__ bin,
           const float* __restrict__ Wout, const float* __restrict__ bout,
           const float* __restrict__ lng, const float* __restrict__ lnb,
           const float* __restrict__ maskV,
           float* __restrict__ out)
{
    __shared__ float sX[16 * 128];
    __shared__ float sH[16 * 512];
    const int tid  = threadIdx.x;
    const int row0 = blockIdx.x * 16;

    for (int idx = tid; idx < 16 * 128; idx += 256)
        sX[idx] = g_hV1[(size_t)row0 * 128 + idx];
    __syncthreads();

    {
        const int j0 = tid * 2;
        float acc[16][2];
        #pragma unroll
        for (int r = 0; r < 16; r++) { acc[r][0] = bin[j0]; acc[r][1] = bin[j0 + 1]; }
        #pragma unroll 2
        for (int i = 0; i < 128; i++) {
            float2 w = *reinterpret_cast<const float2*>(Win + i * FFD + j0);
            #pragma unroll
            for (int r = 0; r < 16; r++) {
                float a = sX[r * 128 + i];
                acc[r][0] = fmaf(a, w.x, acc[r][0]);
                acc[r][1] = fmaf(a, w.y, acc[r][1]);
            }
        }
        #pragma unroll
        for (int r = 0; r < 16; r++) {
            sH[r * FFD + j0]     = gelu_exact(acc[r][0]);
            sH[r * FFD + j0 + 1] = gelu_exact(acc[r][1]);
        }
    }
    __syncthreads();

    {
        const int j = tid & 127, rh = tid >> 7;
        float acc[8];
        #pragma unroll
        for (int r = 0; r < 8; r++) acc[r] = bout[j];
        #pragma unroll 2
        for (int i = 0; i < FFD; i++) {
            float w = Wout[i * 128 + j];
            #pragma unroll
            for (int r = 0; r < 8; r++)
                acc[r] = fmaf(sH[(rh * 8 + r) * FFD + i], w, acc[r]);
        }
        #pragma unroll
        for (int r = 0; r < 8; r++)
            sX[(rh * 8 + r) * 128 + j] += acc[r];
    }
    __syncthreads();

    int w = tid >> 5, lane = tid & 31;
    for (int r = w; r < 16; r += 8) {
        float v[4];
        #pragma unroll
        for (int u = 0; u < 4; u++) v[u] = sX[r * 128 + lane + 32 * u];
        float s  = v[0] + v[1] + v[2] + v[3];
        float ss = v[0]*v[0] + v[1]*v[1] + v[2]*v[2] + v[3]*v[3];
        #pragma unroll
        for (int o = 16; o; o >>= 1) {
            s  += __shfl_xor_sync(0xffffffffu, s, o);
            ss += __shfl_xor_sync(0xffffffffu, ss, o);
        }
        float mean = s * (1.0f / 128.0f);
        float rstd = rsqrtf(ss * (1.0f / 128.0f) - mean * mean + 1e-5f);
        float mk = maskV[row0 + r];
        #pragma unroll
        for (int u = 0; u < 4; u++) {
            int c = lane + 32 * u;
            float val = mk * ((v[u] - mean) * rstd * lng[c] + lnb[c]);
            size_t gi = ((size_t)row0 + r) * 128 + c;
            out[gi] = val;
            __nv_bfloat16 h = __float2bfloat16(val);
            g_hV2hi[gi] = h;
            g_hV2lo[gi] = __float2bfloat16(val - __bfloat162float(h));
        }
    }
}

extern "C" void kernel_launch(void* const* d_in, const int* in_sizes, int n_in,
                              void* d_out, int out_size)
{
    const float* hV    = (const float*)d_in[0];
    const float* hE    = (const float*)d_in[1];
    const void*  Eidx  = d_in[2];
    const float* maskV = (const float*)d_in[3];
    const float* maskA = (const float*)d_in[4];
    const float* W1w  = (const float*)d_in[5],  *W1b  = (const float*)d_in[6];
    const float* W2w  = (const float*)d_in[7],  *W2b  = (const float*)d_in[8];
    const float* W3w  = (const float*)d_in[9],  *W3b  = (const float*)d_in[10];
    const float* W11w = (const float*)d_in[11], *W11b = (const float*)d_in[12];
    const float* W12w = (const float*)d_in[13], *W12b = (const float*)d_in[14];
    const float* W13w = (const float*)d_in[15], *W13b = (const float*)d_in[16];
    const float* Winw = (const float*)d_in[17], *Winb = (const float*)d_in[18];
    const float* Woutw= (const float*)d_in[19], *Woutb= (const float*)d_in[20];
    const float* ln1g = (const float*)d_in[21], *ln1b = (const float*)d_in[22];
    const float* ln2g = (const float*)d_in[23], *ln2b = (const float*)d_in[24];
    const float* ln3g = (const float*)d_in[25], *ln3b = (const float*)d_in[26];

    float* out_hV = (float*)d_out;
    float* out_hE = out_hV + (size_t)BN * HH;

    cudaFuncSetAttribute(gemm_msg_kernel<false>, cudaFuncAttributeMaxDynamicSharedMemorySize, SM_TOTAL);
    cudaFuncSetAttribute(gemm_msg_kernel<true>,  cudaFuncAttributeMaxDynamicSharedMemorySize, SM_TOTAL);

    __nv_bfloat16 *vhi, *vlo, *v2hi, *v2lo;
    cudaGetSymbolAddress((void**)&vhi,  g_hVhi);
    cudaGetSymbolAddress((void**)&vlo,  g_hVlo);
    cudaGetSymbolAddress((void**)&v2hi, g_hV2hi);
    cudaGetSymbolAddress((void**)&v2lo, g_hV2lo);

    detect_idx_kernel<<<1, 1>>>((const int*)Eidx);
    prep_all<<<PW_BLKS + PV_BLKS, 256>>>(W1w, W2w, W3w, W11w, W12w, W13w, hV);
    cw_kernel<<<BN, 128>>>(hV, W1w, W1b);
    gemm_msg_kernel<false><<<NCTA, NTHR, SM_TOTAL>>>(
        vhi, vlo, hE, Eidx, maskA, W2b, W3b, 0, nullptr, nullptr, nullptr);
    reduce_ln1<<<BN, 128>>>(hV, ln1g, ln1b);
    ffn_kernel<<<BN / 16, 256>>>(Winw, Winb, Woutw, Woutb, ln2g, ln2b, maskV, out_hV);
    cw_kernel<<<BN, 128>>>(out_hV, W11w, W11b);
    gemm_msg_kernel<true><<<NCTA, NTHR, SM_TOTAL>>>(
        v2hi, v2lo, hE, Eidx, maskA, W12b, W13b, WMSG, ln3g, ln3b, out_hE);

    (void)in_sizes; (void)n_in; (void)out_size;
}

// round 11
// speedup vs baseline: 1.2649x; 1.2649x over previous
#include <cuda_runtime.h>
#include <cuda_bf16.h>
#include <cstdint>

#define BB  2
#define NN  1024
#define KK  48
#define HH  128
#define FFD 512
#define BN  (BB*NN)
#define NEDGE (BN*KK)          // 98304
#define MT  128
#define NCTA (NEDGE/MT)        // 768
#define NTHR 512

// smem: tiles are 128x64 bf16 = 16KB, 128B rows (SW128)
#define TILE_B  16384
#define SM_B    1024
#define SM_A2   (SM_B  + 4*TILE_B)
#define SM_A3   (SM_A2 + 4*TILE_B)
#define SM_TOTAL (SM_A3 + 4*TILE_B)        // 197632

#define WOFF_G1 0
#define WOFF_G2 (384*HH)
#define WOFF_G3 (WOFF_G2 + 128*HH)
#define WMSG    (WOFF_G3 + 128*HH)

__device__ float g_hV1[BN*HH];
__device__ float g_m[(size_t)NEDGE*HH];
__device__ float g_cw[BN*HH];
__device__ __align__(16) __nv_bfloat16 g_WThi[2*WMSG];
__device__ __align__(16) __nv_bfloat16 g_WTlo[2*WMSG];
__device__ __align__(16) __nv_bfloat16 g_hVhi[BN*HH],  g_hVlo[BN*HH];
__device__ __align__(16) __nv_bfloat16 g_hV2hi[BN*HH], g_hV2lo[BN*HH];
__device__ int g_idx64;

__device__ __forceinline__ float gelu_exact(float x) {
    return 0.5f * x * (1.0f + erff(x * 0.70710678118654752f));
}

__global__ void detect_idx_kernel(const int* __restrict__ e32) {
    int all0 = 1;
    #pragma unroll
    for (int i = 1; i < 96; i += 2) all0 &= (e32[i] == 0);
    g_idx64 = all0;
}

__device__ __forceinline__ int load_nbidx(const void* Eidx, int is64, long long pos) {
    int v;
    if (is64) v = (int)((const long long*)Eidx)[pos];
    else      v = ((const int*)Eidx)[pos];
    v = v < 0 ? 0 : (v >= NN ? NN - 1 : v);
    return v;
}

// -------- prep: 6 weight transposes + hV split --------
#define PW_BLKS 640
#define PV_BLKS 256
__global__ void __launch_bounds__(256)
prep_all(const float* __restrict__ W1,  const float* __restrict__ W2,
         const float* __restrict__ W3,  const float* __restrict__ W11,
         const float* __restrict__ W12, const float* __restrict__ W13,
         const float* __restrict__ hV)
{
    int blk = blockIdx.x, tid = threadIdx.x;
    if (blk < PW_BLKS) {
        int id = blk * 256 + tid;
        const float* src; int base, K;
        if      (id < 49152)  { src = W1;  base = 0;      K = 384; }
        else if (id < 65536)  { src = W2;  base = 49152;  K = 128; }
        else if (id < 81920)  { src = W3;  base = 65536;  K = 128; }
        else if (id < 131072) { src = W11; base = 81920;  K = 384; }
        else if (id < 147456) { src = W12; base = 131072; K = 128; }
        else                  { src = W13; base = 147456; K = 128; }
        int local = id - base;
        int k = local >> 7, n = local & 127;
        float x = src[local];
        __nv_bfloat16 h = __float2bfloat16(x);
        g_WThi[base + (size_t)n * K + k] = h;
        g_WTlo[base + (size_t)n * K + k] = __float2bfloat16(x - __bfloat162float(h));
    } else {
        int idx = (blk - PW_BLKS) * 256 + tid;
        float4 v = ((const float4*)hV)[idx];
        __nv_bfloat16 h0 = __float2bfloat16(v.x), h1 = __float2bfloat16(v.y);
        __nv_bfloat16 h2 = __float2bfloat16(v.z), h3 = __float2bfloat16(v.w);
        __nv_bfloat162* ph = (__nv_bfloat162*)(g_hVhi + (size_t)idx * 4);
        __nv_bfloat162* pl = (__nv_bfloat162*)(g_hVlo + (size_t)idx * 4);
        ph[0] = __nv_bfloat162(h0, h1); ph[1] = __nv_bfloat162(h2, h3);
        pl[0] = __nv_bfloat162(__float2bfloat16(v.x - __bfloat162float(h0)),
                               __float2bfloat16(v.y - __bfloat162float(h1)));
        pl[1] = __nv_bfloat162(__float2bfloat16(v.z - __bfloat162float(h2)),
                               __float2bfloat16(v.w - __bfloat162float(h3)));
    }
}

// -------- cw: g_cw[bn][j] = bias[j] + center . Wtop[:,j] --------
__global__ void __launch_bounds__(128)
cw_kernel(const float* __restrict__ center, const float* __restrict__ Wtop,
          const float* __restrict__ bias)
{
    __shared__ float sc[128];
    int bn = blockIdx.x, j = threadIdx.x;
    sc[j] = center[(size_t)bn * HH + j];
    __syncthreads();
    float acc = bias[j];
    #pragma unroll 8
    for (int i = 0; i < 128; i++) acc = fmaf(sc[i], Wtop[i * HH + j], acc);
    g_cw[(size_t)bn * HH + j] = acc;
}

// ---------------- PTX helpers ----------------
__device__ __forceinline__ uint32_t smem_u32(const void* p) {
    uint32_t a;
    asm("{ .reg .u64 t; cvta.to.shared.u64 t, %1; cvt.u32.u64 %0, t; }" : "=r"(a) : "l"(p));
    return a;
}
__device__ __forceinline__ uint32_t sw128(uint32_t off) {
    return off ^ ((off >> 3) & 0x70);
}
__device__ __forceinline__ void cp_async16(uint32_t dst, const void* src) {
    asm volatile("cp.async.cg.shared.global [%0], [%1], 16;" :: "r"(dst), "l"(src));
}
#define CP_WAIT_ALL() asm volatile("cp.async.wait_all;" ::: "memory")
__device__ __forceinline__ void ldsm4(uint32_t* r, uint32_t addr) {
    asm volatile("ldmatrix.sync.aligned.m8n8.x4.shared.b16 {%0,%1,%2,%3}, [%4];"
        : "=r"(r[0]), "=r"(r[1]), "=r"(r[2]), "=r"(r[3]) : "r"(addr));
}
__device__ __forceinline__ void mma16816(float* d, const uint32_t* a, const uint32_t* b) {
    asm volatile("mma.sync.aligned.m16n8k16.row.col.f32.bf16.bf16.f32 "
        "{%0,%1,%2,%3}, {%4,%5,%6,%7}, {%8,%9}, {%0,%1,%2,%3};"
        : "+f"(d[0]), "+f"(d[1]), "+f"(d[2]), "+f"(d[3])
        : "r"(a[0]), "r"(a[1]), "r"(a[2]), "r"(a[3]), "r"(b[0]), "r"(b[1]));
}
__device__ __forceinline__ void ldsmA(uint32_t* r, uint32_t tbase, int mrow, int klo, int lane) {
    int q = lane >> 3;
    int row = mrow + (lane & 7) + 8 * (q & 1);
    int kk  = klo + 8 * (q >> 1);
    ldsm4(r, tbase + sw128((uint32_t)(row * 128 + kk * 2)));
}
__device__ __forceinline__ void ldsmB(uint32_t* r, uint32_t tbase, int nrow0, int klo, int lane) {
    int q = lane >> 3;
    int row = nrow0 + (lane & 7) + 8 * (q >> 1);
    int kk  = klo + 8 * (q & 1);
    ldsm4(r, tbase + sw128((uint32_t)(row * 128 + kk * 2)));
}
__device__ __forceinline__ uint32_t pack_bf2(__nv_bfloat16 a, __nv_bfloat16 b) {
    return (uint32_t)__bfloat16_as_ushort(a) | ((uint32_t)__bfloat16_as_ushort(b) << 16);
}
__device__ __forceinline__ void split2(float x, float y, uint32_t& hi, uint32_t& lo) {
    __nv_bfloat16 hx = __float2bfloat16(x), hy = __float2bfloat16(y);
    __nv_bfloat16 lx = __float2bfloat16(x - __bfloat162float(hx));
    __nv_bfloat16 ly = __float2bfloat16(y - __bfloat162float(hy));
    hi = pack_bf2(hx, hy);
    lo = pack_bf2(lx, ly);
}

// warp tile 32(m) x 32(n): acc[2][4][4]; per k16: 8 LDSM vs 24 HMMA
__device__ __forceinline__ void mma_chunk(uint32_t aHi, uint32_t aLo,
                                          uint32_t bHi, uint32_t bLo,
                                          int m0, int n0, int lane,
                                          float acc[2][4][4]) {
    #pragma unroll
    for (int ks = 0; ks < 4; ks++) {
        int klo = ks * 16;
        uint32_t Ah[2][4], Al[2][4];
        #pragma unroll
        for (int mt = 0; mt < 2; mt++) {
            ldsmA(Ah[mt], aHi, m0 + 16 * mt, klo, lane);
            ldsmA(Al[mt], aLo, m0 + 16 * mt, klo, lane);
        }
        uint32_t Bh[2][4], Bl[2][4];
        #pragma unroll
        for (int p = 0; p < 2; p++) {
            ldsmB(Bh[p], bHi, n0 + p * 16, klo, lane);
            ldsmB(Bl[p], bLo, n0 + p * 16, klo, lane);
        }
        #pragma unroll
        for (int mt = 0; mt < 2; mt++) {
            #pragma unroll
            for (int p = 0; p < 2; p++) {
                #pragma unroll
                for (int s = 0; s < 2; s++) {
                    int nt = p * 2 + s;
                    mma16816(acc[mt][nt], Ah[mt], &Bh[p][s * 2]);
                    mma16816(acc[mt][nt], Ah[mt], &Bl[p][s * 2]);
                    mma16816(acc[mt][nt], Al[mt], &Bh[p][s * 2]);
                }
            }
        }
    }
}

// ---------------- fused GEMM-chain message kernel (512 threads, 4m x 4n warps) ----------------
template<bool EDGE>
__global__ void __launch_bounds__(NTHR, 1)
gemm_msg_kernel(const __nv_bfloat16* __restrict__ vhi,
                const __nv_bfloat16* __restrict__ vlo,
                const float* __restrict__ hE,
                const void*  __restrict__ Eidx,
                const float* __restrict__ maskA,
                const float* __restrict__ bb, const float* __restrict__ bc,
                int wbase,
                const float* __restrict__ lng, const float* __restrict__ lnb,
                float* __restrict__ out)
{
    extern __shared__ uint8_t smem8[];
    const int tid  = threadIdx.x;
    const int wid  = tid >> 5;
    const int lane = tid & 31;
    const int e0   = blockIdx.x * MT;
    const int is64 = g_idx64;
    const uint32_t sbase = smem_u32(smem8);

    const int m0 = (wid & 3) * 32;    // 4 m-warps
    const int n0 = (wid >> 2) * 32;   // 4 n-warps

    const __nv_bfloat16* WTh = g_WThi + wbase;
    const __nv_bfloat16* WTl = g_WTlo + wbase;

    float acc[2][4][4];
    auto zero_acc = [&]() {
        #pragma unroll
        for (int mt = 0; mt < 2; mt++)
            #pragma unroll
            for (int nt = 0; nt < 4; nt++)
                #pragma unroll
                for (int i = 0; i < 4; i++) acc[mt][nt][i] = 0.f;
    };

    // B fill via cp.async (pre-split weights, 16B lines)
    auto fill_B = [&](int woff, int Klen, int kbase, int slot) {
        const __nv_bfloat16* bh = WTh + woff;
        const __nv_bfloat16* bl = WTl + woff;
        int u = tid & 7;
        uint32_t dh = sbase + SM_B + slot * TILE_B;
        uint32_t dl = sbase + SM_B + (2 + slot) * TILE_B;
        #pragma unroll
        for (int n = tid >> 3; n < 128; n += 64) {
            uint32_t sw = sw128((uint32_t)n * 128 + u * 16);
            cp_async16(dh + sw, bh + (size_t)n * Klen + kbase + u * 8);
            cp_async16(dl + sw, bl + (size_t)n * Klen + kbase + u * 8);
        }
    };

    auto fill_A = [&](int ch, int buf) {
        if (ch < 2) {
            // hE fp32 -> split on the fly (sync path)
            uint8_t* aH = smem8 + SM_A3 + (2 * buf) * TILE_B;
            uint8_t* aL = smem8 + SM_A3 + (2 * buf + 1) * TILE_B;
            int c4 = tid & 15;
            #pragma unroll
            for (int r = tid >> 4; r < MT; r += 32) {
                int e = e0 + r;
                const float* src = hE + (size_t)e * HH + ch * 64;
                float4 v = *((const float4*)src + c4);
                uint32_t h01, l01, h23, l23;
                split2(v.x, v.y, h01, l01);
                split2(v.z, v.w, h23, l23);
                uint32_t sw = sw128((uint32_t)r * 128 + c4 * 8);
                *(uint2*)(aH + sw) = make_uint2(h01, h23);
                *(uint2*)(aL + sw) = make_uint2(l01, l23);
            }
        } else {
            // neighbor pre-split bf16 (cp.async path)
            uint32_t aH = sbase + SM_A3 + (2 * buf) * TILE_B;
            uint32_t aL = sbase + SM_A3 + (2 * buf + 1) * TILE_B;
            int u = tid & 7;
            #pragma unroll
            for (int r = tid >> 3; r < MT; r += 64) {
                int e = e0 + r;
                int b  = e / (KK * NN);
                int nb = load_nbidx(Eidx, is64, e);
                size_t off = ((size_t)b * NN + nb) * HH + (ch - 2) * 64 + u * 8;
                uint32_t sw = sw128((uint32_t)r * 128 + u * 16);
                cp_async16(aH + sw, vhi + off);
                cp_async16(aL + sw, vlo + off);
            }
        }
    };

    auto epi_act = [&](const float* __restrict__ bias, bool useCW, uint32_t dstOff) {
        #pragma unroll
        for (int mt = 0; mt < 2; mt++) {
            int row = m0 + mt * 16 + (lane >> 2);
            const float* cw0 = nullptr; const float* cw1 = nullptr;
            if (useCW) {
                cw0 = g_cw + (size_t)((e0 + row) / KK) * HH;
                cw1 = g_cw + (size_t)((e0 + row + 8) / KK) * HH;
            }
            #pragma unroll
            for (int nt = 0; nt < 4; nt++) {
                int c0 = n0 + nt * 8 + 2 * (lane & 3);
                float b00, b01, b10, b11;
                if (useCW) { b00 = cw0[c0]; b01 = cw0[c0 + 1]; b10 = cw1[c0]; b11 = cw1[c0 + 1]; }
                else       { b00 = b10 = bias[c0]; b01 = b11 = bias[c0 + 1]; }
                int kt = c0 >> 6, kk = c0 & 63;
                uint8_t* dH = smem8 + dstOff + kt * TILE_B;
                uint8_t* dL = smem8 + dstOff + (2 + kt) * TILE_B;
                float x0 = gelu_exact(acc[mt][nt][0] + b00);
                float y0 = gelu_exact(acc[mt][nt][1] + b01);
                float x1 = gelu_exact(acc[mt][nt][2] + b10);
                float y1 = gelu_exact(acc[mt][nt][3] + b11);
                uint32_t hi, lo;
                split2(x0, y0, hi, lo);
                uint32_t sw = sw128((uint32_t)(row * 128 + kk * 2));
                *(uint32_t*)(dH + sw) = hi; *(uint32_t*)(dL + sw) = lo;
                split2(x1, y1, hi, lo);
                sw = sw128((uint32_t)((row + 8) * 128 + kk * 2));
                *(uint32_t*)(dH + sw) = hi; *(uint32_t*)(dL + sw) = lo;
            }
        }
    };

    // ===== GEMM1: K=256 (hE + nbr), 4 chunks, double-buffered, async fills =====
    zero_acc();
    fill_A(0, 0);
    fill_B(WOFF_G1, 384, 128, 0);
    CP_WAIT_ALL();
    __syncthreads();
    #pragma unroll 1
    for (int ch = 0; ch < 4; ch++) {
        int bi = ch & 1;
        if (ch < 3) {
            fill_A(ch + 1, bi ^ 1);
            fill_B(WOFF_G1, 384, 128 + (ch + 1) * 64, bi ^ 1);
        }
        mma_chunk(sbase + SM_A3 + (2 * bi) * TILE_B,
                  sbase + SM_A3 + (2 * bi + 1) * TILE_B,
                  sbase + SM_B + bi * TILE_B,
                  sbase + SM_B + (2 + bi) * TILE_B, m0, n0, lane, acc);
        CP_WAIT_ALL();
        __syncthreads();
    }

    // ===== epilogue1 (+cw) + async B fill for GEMM2 =====
    fill_B(WOFF_G2, 128, 0, 0);
    fill_B(WOFF_G2, 128, 64, 1);
    epi_act(nullptr, true, SM_A2);
    zero_acc();
    CP_WAIT_ALL();
    __syncthreads();

    // ===== GEMM2 =====
    #pragma unroll
    for (int kt = 0; kt < 2; kt++)
        mma_chunk(sbase + SM_A2 + kt * TILE_B, sbase + SM_A2 + (2 + kt) * TILE_B,
                  sbase + SM_B  + kt * TILE_B, sbase + SM_B  + (2 + kt) * TILE_B,
                  m0, n0, lane, acc);
    __syncthreads();

    // ===== epilogue2 + async B fill for GEMM3 =====
    fill_B(WOFF_G3, 128, 0, 0);
    fill_B(WOFF_G3, 128, 64, 1);
    epi_act(bb, false, SM_A3);
    zero_acc();
    CP_WAIT_ALL();
    __syncthreads();

    // ===== GEMM3 =====
    #pragma unroll
    for (int kt = 0; kt < 2; kt++)
        mma_chunk(sbase + SM_A3 + kt * TILE_B, sbase + SM_A3 + (2 + kt) * TILE_B,
                  sbase + SM_B  + kt * TILE_B, sbase + SM_B  + (2 + kt) * TILE_B,
                  m0, n0, lane, acc);
    __syncthreads();   // B region dead -> fp32 staging

    float* sOut = (float*)(smem8 + SM_B);
    {
        #pragma unroll
        for (int mt = 0; mt < 2; mt++) {
            int row = m0 + mt * 16 + (lane >> 2);
            float mk0 = 1.f, mk1 = 1.f;
            if (!EDGE) { mk0 = maskA[e0 + row]; mk1 = maskA[e0 + row + 8]; }
            #pragma unroll
            for (int nt = 0; nt < 4; nt++) {
                int c0 = n0 + nt * 8 + 2 * (lane & 3);
                float b0v = bc[c0], b1v = bc[c0 + 1];
                sOut[row * 128 + c0]           = (acc[mt][nt][0] + b0v) * mk0;
                sOut[row * 128 + c0 + 1]       = (acc[mt][nt][1] + b1v) * mk0;
                sOut[(row + 8) * 128 + c0]     = (acc[mt][nt][2] + b0v) * mk1;
                sOut[(row + 8) * 128 + c0 + 1] = (acc[mt][nt][3] + b1v) * mk1;
            }
        }
        __syncthreads();
    }

    if (!EDGE) {
        float4* d4 = (float4*)(g_m + (size_t)e0 * HH);
        const float4* s4 = (const float4*)sOut;
        #pragma unroll
        for (int p = 0; p < 8; p++) d4[tid + p * NTHR] = s4[tid + p * NTHR];
    } else {
        for (int r = wid; r < MT; r += 16) {
            const float* her = hE + (size_t)(e0 + r) * HH;
            float v[4];
            #pragma unroll
            for (int u = 0; u < 4; u++) {
                int c = lane + 32 * u;
                v[u] = sOut[r * 128 + c] + her[c];
            }
            float s  = v[0] + v[1] + v[2] + v[3];
            float ss = v[0]*v[0] + v[1]*v[1] + v[2]*v[2] + v[3]*v[3];
            #pragma unroll
            for (int o = 16; o; o >>= 1) {
                s  += __shfl_xor_sync(0xffffffffu, s, o);
                ss += __shfl_xor_sync(0xffffffffu, ss, o);
            }
            float mean = s * (1.0f / 128.0f);
            float rstd = rsqrtf(ss * (1.0f / 128.0f) - mean * mean + 1e-5f);
            #pragma unroll
            for (int u = 0; u < 4; u++) {
                int c = lane + 32 * u;
                out[(size_t)(e0 + r) * HH + c] = (v[u] - mean) * rstd * lng[c] + lnb[c];
            }
        }
    }
}

// ---------------- node reduction + LN1 ----------------
__global__ void __launch_bounds__(128)
reduce_ln1(const float* __restrict__ hV,
           const float* __restrict__ lng, const float* __restrict__ lnb)
{
    int bn = blockIdx.x, j = threadIdx.x;
    int w = j >> 5, lane = j & 31;
    float s = 0.f;
    const float* mp = g_m + (size_t)bn * KK * HH + j;
    #pragma unroll 8
    for (int k = 0; k < KK; k++) s += mp[(size_t)k * HH];
    float v = hV[(size_t)bn * HH + j] + s * (1.0f / 48.0f);

    __shared__ float rs[4], rq[4];
    float a = v, q = v * v;
    #pragma unroll
    for (int o = 16; o; o >>= 1) {
        a += __shfl_xor_sync(0xffffffffu, a, o);
        q += __shfl_xor_sync(0xffffffffu, q, o);
    }
    if (lane == 0) { rs[w] = a; rq[w] = q; }
    __syncthreads();
    float S = rs[0] + rs[1] + rs[2] + rs[3];
    float Q = rq[0] + rq[1] + rq[2] + rq[3];
    float mean = S * (1.0f / 128.0f);
    float rstd = rsqrtf(Q * (1.0f / 128.0f) - mean * mean + 1e-5f);
    g_hV1[(size_t)bn * HH + j] = (v - mean) * rstd * lng[j] + lnb[j];
}

// ---------------- FFN + LN2 + mask_V (+ bf16 split of h_Vn) ----------------
__global__ void __launch_bounds__(256, 1)
ffn_kernel(const float* __restrict__ Win, const float* __restrict__ bin,
           const float* __restrict__ Wout, const float* __restrict__ bout,
           const float* __restrict__ lng, const float* __restrict__ lnb,
           const float* __restrict__ maskV,
           float* __restrict__ out)
{
    __shared__ float sX[16 * 128];
    __shared__ float sH[16 * 512];
    const int tid  = threadIdx.x;
    const int row0 = blockIdx.x * 16;

    for (int idx = tid; idx < 16 * 128; idx += 256)
        sX[idx] = g_hV1[(size_t)row0 * 128 + idx];
    __syncthreads();

    {
        const int j0 = tid * 2;
        float acc[16][2];
        #pragma unroll
        for (int r = 0; r < 16; r++) { acc[r][0] = bin[j0]; acc[r][1] = bin[j0 + 1]; }
        #pragma unroll 2
        for (int i = 0; i < 128; i++) {
            float2 w = *reinterpret_cast<const float2*>(Win + i * FFD + j0);
            #pragma unroll
            for (int r = 0; r < 16; r++) {
                float a = sX[r * 128 + i];
                acc[r][0] = fmaf(a, w.x, acc[r][0]);
                acc[r][1] = fmaf(a, w.y, acc[r][1]);
            }
        }
        #pragma unroll
        for (int r = 0; r < 16; r++) {
            sH[r * FFD + j0]     = gelu_exact(acc[r][0]);
            sH[r * FFD + j0 + 1] = gelu_exact(acc[r][1]);
        }
    }
    __syncthreads();

    {
        const int j = tid & 127, rh = tid >> 7;
        float acc[8];
        #pragma unroll
        for (int r = 0; r < 8; r++) acc[r] = bout[j];
        #pragma unroll 2
        for (int i = 0; i < FFD; i++) {
            float w = Wout[i * 128 + j];
            #pragma unroll
            for (int r = 0; r < 8; r++)
                acc[r] = fmaf(sH[(rh * 8 + r) * FFD + i], w, acc[r]);
        }
        #pragma unroll
        for (int r = 0; r < 8; r++)
            sX[(rh * 8 + r) * 128 + j] += acc[r];
    }
    __syncthreads();

    int w = tid >> 5, lane = tid & 31;
    for (int r = w; r < 16; r += 8) {
        float v[4];
        #pragma unroll
        for (int u = 0; u < 4; u++) v[u] = sX[r * 128 + lane + 32 * u];
        float s  = v[0] + v[1] + v[2] + v[3];
        float ss = v[0]*v[0] + v[1]*v[1] + v[2]*v[2] + v[3]*v[3];
        #pragma unroll
        for (int o = 16; o; o >>= 1) {
            s  += __shfl_xor_sync(0xffffffffu, s, o);
            ss += __shfl_xor_sync(0xffffffffu, ss, o);
        }
        float mean = s * (1.0f / 128.0f);
        float rstd = rsqrtf(ss * (1.0f / 128.0f) - mean * mean + 1e-5f);
        float mk = maskV[row0 + r];
        #pragma unroll
        for (int u = 0; u < 4; u++) {
            int c = lane + 32 * u;
            float val = mk * ((v[u] - mean) * rstd * lng[c] + lnb[c]);
            size_t gi = ((size_t)row0 + r) * 128 + c;
            out[gi] = val;
            __nv_bfloat16 h = __float2bfloat16(val);
            g_hV2hi[gi] = h;
            g_hV2lo[gi] = __float2bfloat16(val - __bfloat162float(h));
        }
    }
}

extern "C" void kernel_launch(void* const* d_in, const int* in_sizes, int n_in,
                              void* d_out, int out_size)
{
    const float* hV    = (const float*)d_in[0];
    const float* hE    = (const float*)d_in[1];
    const void*  Eidx  = d_in[2];
    const float* maskV = (const float*)d_in[3];
    const float* maskA = (const float*)d_in[4];
    const float* W1w  = (const float*)d_in[5],  *W1b  = (const float*)d_in[6];
    const float* W2w  = (const float*)d_in[7],  *W2b  = (const float*)d_in[8];
    const float* W3w  = (const float*)d_in[9],  *W3b  = (const float*)d_in[10];
    const float* W11w = (const float*)d_in[11], *W11b = (const float*)d_in[12];
    const float* W12w = (const float*)d_in[13], *W12b = (const float*)d_in[14];
    const float* W13w = (const float*)d_in[15], *W13b = (const float*)d_in[16];
    const float* Winw = (const float*)d_in[17], *Winb = (const float*)d_in[18];
    const float* Woutw= (const float*)d_in[19], *Woutb= (const float*)d_in[20];
    const float* ln1g = (const float*)d_in[21], *ln1b = (const float*)d_in[22];
    const float* ln2g = (const float*)d_in[23], *ln2b = (const float*)d_in[24];
    const float* ln3g = (const float*)d_in[25], *ln3b = (const float*)d_in[26];

    float* out_hV = (float*)d_out;
    float* out_hE = out_hV + (size_t)BN * HH;

    cudaFuncSetAttribute(gemm_msg_kernel<false>, cudaFuncAttributeMaxDynamicSharedMemorySize, SM_TOTAL);
    cudaFuncSetAttribute(gemm_msg_kernel<true>,  cudaFuncAttributeMaxDynamicSharedMemorySize, SM_TOTAL);

    __nv_bfloat16 *vhi, *vlo, *v2hi, *v2lo;
    cudaGetSymbolAddress((void**)&vhi,  g_hVhi);
    cudaGetSymbolAddress((void**)&vlo,  g_hVlo);
    cudaGetSymbolAddress((void**)&v2hi, g_hV2hi);
    cudaGetSymbolAddress((void**)&v2lo, g_hV2lo);

    detect_idx_kernel<<<1, 1>>>((const int*)Eidx);
    prep_all<<<PW_BLKS + PV_BLKS, 256>>>(W1w, W2w, W3w, W11w, W12w, W13w, hV);
    cw_kernel<<<BN, 128>>>(hV, W1w, W1b);
    gemm_msg_kernel<false><<<NCTA, NTHR, SM_TOTAL>>>(
        vhi, vlo, hE, Eidx, maskA, W2b, W3b, 0, nullptr, nullptr, nullptr);
    reduce_ln1<<<BN, 128>>>(hV, ln1g, ln1b);
    ffn_kernel<<<BN / 16, 256>>>(Winw, Winb, Woutw, Woutb, ln2g, ln2b, maskV, out_hV);
    cw_kernel<<<BN, 128>>>(out_hV, W11w, W11b);
    gemm_msg_kernel<true><<<NCTA, NTHR, SM_TOTAL>>>(
        v2hi, v2lo, hE, Eidx, maskA, W12b, W13b, WMSG, ln3g, ln3b, out_hE);

    (void)in_sizes; (void)n_in; (void)out_size;
}

// round 12
// speedup vs baseline: 1.4182x; 1.1212x over previous
#include <cuda_runtime.h>
#include <cuda_bf16.h>
#include <cstdint>

#define BB  2
#define NN  1024
#define KK  48
#define HH  128
#define FFD 512
#define BN  (BB*NN)
#define NEDGE (BN*KK)          // 98304
#define MT  64
#define NCTA (NEDGE/MT)        // 1536
#define NTHR 256

// smem tiles: A = 64 rows x 64k bf16 (8KB, 128B rows, SW128); W = 128n x 64k bf16 (16KB)
#define TILE_A  8192
#define TILE_W  16384
#define SM_B    1024                       // 2 tiles: hi, lo (single-buffered)
#define SM_A2   (SM_B  + 2*TILE_W)         // 33792: 4 tiles k0hi,k1hi,k0lo,k1lo
#define SM_A3   (SM_A2 + 4*TILE_A)         // 66560: 4 tiles (GEMM1 ping-pong slots)
#define SM_TOTAL (SM_A3 + 4*TILE_A)        // 99328

#define WOFF_G1 0
#define WOFF_G2 (384*HH)
#define WOFF_G3 (WOFF_G2 + 128*HH)
#define WMSG    (WOFF_G3 + 128*HH)

__device__ float g_hV1[BN*HH];
__device__ float g_m[(size_t)NEDGE*HH];
__device__ float g_cw[BN*HH];
__device__ __align__(16) __nv_bfloat16 g_WThi[2*WMSG];
__device__ __align__(16) __nv_bfloat16 g_WTlo[2*WMSG];
__device__ __align__(16) __nv_bfloat16 g_hVhi[BN*HH],  g_hVlo[BN*HH];
__device__ __align__(16) __nv_bfloat16 g_hV2hi[BN*HH], g_hV2lo[BN*HH];
__device__ int g_idx64;

__device__ __forceinline__ float gelu_exact(float x) {
    return 0.5f * x * (1.0f + erff(x * 0.70710678118654752f));
}

__global__ void detect_idx_kernel(const int* __restrict__ e32) {
    int all0 = 1;
    #pragma unroll
    for (int i = 1; i < 96; i += 2) all0 &= (e32[i] == 0);
    g_idx64 = all0;
}

__device__ __forceinline__ int load_nbidx(const void* Eidx, int is64, long long pos) {
    int v;
    if (is64) v = (int)((const long long*)Eidx)[pos];
    else      v = ((const int*)Eidx)[pos];
    v = v < 0 ? 0 : (v >= NN ? NN - 1 : v);
    return v;
}

// -------- prep: 6 weight transposes + hV split --------
#define PW_BLKS 640
#define PV_BLKS 256
__global__ void __launch_bounds__(256)
prep_all(const float* __restrict__ W1,  const float* __restrict__ W2,
         const float* __restrict__ W3,  const float* __restrict__ W11,
         const float* __restrict__ W12, const float* __restrict__ W13,
         const float* __restrict__ hV)
{
    int blk = blockIdx.x, tid = threadIdx.x;
    if (blk < PW_BLKS) {
        int id = blk * 256 + tid;
        const float* src; int base, K;
        if      (id < 49152)  { src = W1;  base = 0;      K = 384; }
        else if (id < 65536)  { src = W2;  base = 49152;  K = 128; }
        else if (id < 81920)  { src = W3;  base = 65536;  K = 128; }
        else if (id < 131072) { src = W11; base = 81920;  K = 384; }
        else if (id < 147456) { src = W12; base = 131072; K = 128; }
        else                  { src = W13; base = 147456; K = 128; }
        int local = id - base;
        int k = local >> 7, n = local & 127;
        float x = src[local];
        __nv_bfloat16 h = __float2bfloat16(x);
        g_WThi[base + (size_t)n * K + k] = h;
        g_WTlo[base + (size_t)n * K + k] = __float2bfloat16(x - __bfloat162float(h));
    } else {
        int idx = (blk - PW_BLKS) * 256 + tid;
        float4 v = ((const float4*)hV)[idx];
        __nv_bfloat16 h0 = __float2bfloat16(v.x), h1 = __float2bfloat16(v.y);
        __nv_bfloat16 h2 = __float2bfloat16(v.z), h3 = __float2bfloat16(v.w);
        __nv_bfloat162* ph = (__nv_bfloat162*)(g_hVhi + (size_t)idx * 4);
        __nv_bfloat162* pl = (__nv_bfloat162*)(g_hVlo + (size_t)idx * 4);
        ph[0] = __nv_bfloat162(h0, h1); ph[1] = __nv_bfloat162(h2, h3);
        pl[0] = __nv_bfloat162(__float2bfloat16(v.x - __bfloat162float(h0)),
                               __float2bfloat16(v.y - __bfloat162float(h1)));
        pl[1] = __nv_bfloat162(__float2bfloat16(v.z - __bfloat162float(h2)),
                               __float2bfloat16(v.w - __bfloat162float(h3)));
    }
}

// -------- cw: g_cw[bn][j] = bias[j] + center . Wtop[:,j] --------
__global__ void __launch_bounds__(128)
cw_kernel(const float* __restrict__ center, const float* __restrict__ Wtop,
          const float* __restrict__ bias)
{
    __shared__ float sc[128];
    int bn = blockIdx.x, j = threadIdx.x;
    sc[j] = center[(size_t)bn * HH + j];
    __syncthreads();
    float acc = bias[j];
    #pragma unroll 8
    for (int i = 0; i < 128; i++) acc = fmaf(sc[i], Wtop[i * HH + j], acc);
    g_cw[(size_t)bn * HH + j] = acc;
}

// ---------------- PTX helpers ----------------
__device__ __forceinline__ uint32_t smem_u32(const void* p) {
    uint32_t a;
    asm("{ .reg .u64 t; cvta.to.shared.u64 t, %1; cvt.u32.u64 %0, t; }" : "=r"(a) : "l"(p));
    return a;
}
__device__ __forceinline__ uint32_t sw128(uint32_t off) {
    return off ^ ((off >> 3) & 0x70);
}
__device__ __forceinline__ void cp_async16(uint32_t dst, const void* src) {
    asm volatile("cp.async.cg.shared.global [%0], [%1], 16;" :: "r"(dst), "l"(src));
}
#define CP_WAIT_ALL() asm volatile("cp.async.wait_all;" ::: "memory")
__device__ __forceinline__ void ldsm4(uint32_t* r, uint32_t addr) {
    asm volatile("ldmatrix.sync.aligned.m8n8.x4.shared.b16 {%0,%1,%2,%3}, [%4];"
        : "=r"(r[0]), "=r"(r[1]), "=r"(r[2]), "=r"(r[3]) : "r"(addr));
}
__device__ __forceinline__ void mma16816(float* d, const uint32_t* a, const uint32_t* b) {
    asm volatile("mma.sync.aligned.m16n8k16.row.col.f32.bf16.bf16.f32 "
        "{%0,%1,%2,%3}, {%4,%5,%6,%7}, {%8,%9}, {%0,%1,%2,%3};"
        : "+f"(d[0]), "+f"(d[1]), "+f"(d[2]), "+f"(d[3])
        : "r"(a[0]), "r"(a[1]), "r"(a[2]), "r"(a[3]), "r"(b[0]), "r"(b[1]));
}
__device__ __forceinline__ void ldsmA(uint32_t* r, uint32_t tbase, int mrow, int klo, int lane) {
    int q = lane >> 3;
    int row = mrow + (lane & 7) + 8 * (q & 1);
    int kk  = klo + 8 * (q >> 1);
    ldsm4(r, tbase + sw128((uint32_t)(row * 128 + kk * 2)));
}
__device__ __forceinline__ void ldsmB(uint32_t* r, uint32_t tbase, int nrow0, int klo, int lane) {
    int q = lane >> 3;
    int row = nrow0 + (lane & 7) + 8 * (q >> 1);
    int kk  = klo + 8 * (q & 1);
    ldsm4(r, tbase + sw128((uint32_t)(row * 128 + kk * 2)));
}
__device__ __forceinline__ uint32_t pack_bf2(__nv_bfloat16 a, __nv_bfloat16 b) {
    return (uint32_t)__bfloat16_as_ushort(a) | ((uint32_t)__bfloat16_as_ushort(b) << 16);
}
__device__ __forceinline__ void split2(float x, float y, uint32_t& hi, uint32_t& lo) {
    __nv_bfloat16 hx = __float2bfloat16(x), hy = __float2bfloat16(y);
    __nv_bfloat16 lx = __float2bfloat16(x - __bfloat162float(hx));
    __nv_bfloat16 ly = __float2bfloat16(y - __bfloat162float(hy));
    hi = pack_bf2(hx, hy);
    lo = pack_bf2(lx, ly);
}

// warp tile 32(m) x 32(n): acc[2][4][4]; per k16: 8 LDSM vs 24 HMMA
__device__ __forceinline__ void mma_chunk(uint32_t aHi, uint32_t aLo,
                                          uint32_t bHi, uint32_t bLo,
                                          int m0, int n0, int lane,
                                          float acc[2][4][4]) {
    #pragma unroll
    for (int ks = 0; ks < 4; ks++) {
        int klo = ks * 16;
        uint32_t Ah[2][4], Al[2][4];
        #pragma unroll
        for (int mt = 0; mt < 2; mt++) {
            ldsmA(Ah[mt], aHi, m0 + 16 * mt, klo, lane);
            ldsmA(Al[mt], aLo, m0 + 16 * mt, klo, lane);
        }
        uint32_t Bh[2][4], Bl[2][4];
        #pragma unroll
        for (int p = 0; p < 2; p++) {
            ldsmB(Bh[p], bHi, n0 + p * 16, klo, lane);
            ldsmB(Bl[p], bLo, n0 + p * 16, klo, lane);
        }
        #pragma unroll
        for (int mt = 0; mt < 2; mt++) {
            #pragma unroll
            for (int p = 0; p < 2; p++) {
                #pragma unroll
                for (int s = 0; s < 2; s++) {
                    int nt = p * 2 + s;
                    mma16816(acc[mt][nt], Ah[mt], &Bh[p][s * 2]);
                    mma16816(acc[mt][nt], Ah[mt], &Bl[p][s * 2]);
                    mma16816(acc[mt][nt], Al[mt], &Bh[p][s * 2]);
                }
            }
        }
    }
}

// ---------------- fused GEMM-chain message kernel ----------------
// 256 threads = 8 warps (2m x 4n), 64 edge rows per CTA, 2 CTAs/SM.
template<bool EDGE>
__global__ void __launch_bounds__(NTHR, 2)
gemm_msg_kernel(const __nv_bfloat16* __restrict__ vhi,
                const __nv_bfloat16* __restrict__ vlo,
                const float* __restrict__ hE,
                const void*  __restrict__ Eidx,
                const float* __restrict__ maskA,
                const float* __restrict__ bb, const float* __restrict__ bc,
                int wbase,
                const float* __restrict__ lng, const float* __restrict__ lnb,
                float* __restrict__ out)
{
    extern __shared__ uint8_t smem8[];
    const int tid  = threadIdx.x;
    const int wid  = tid >> 5;
    const int lane = tid & 31;
    const int e0   = blockIdx.x * MT;
    const int is64 = g_idx64;
    const uint32_t sbase = smem_u32(smem8);

    const int m0 = (wid & 1) * 32;    // 2 m-warps x 32 rows (64 total)
    const int n0 = (wid >> 1) * 32;   // 4 n-warps x 32 cols

    const __nv_bfloat16* WTh = g_WThi + wbase;
    const __nv_bfloat16* WTl = g_WTlo + wbase;

    float acc[2][4][4];
    auto zero_acc = [&]() {
        #pragma unroll
        for (int mt = 0; mt < 2; mt++)
            #pragma unroll
            for (int nt = 0; nt < 4; nt++)
                #pragma unroll
                for (int i = 0; i < 4; i++) acc[mt][nt][i] = 0.f;
    };

    // B fill (single buffer): hi at SM_B, lo at SM_B + TILE_W. 128n x 64k.
    auto fill_B = [&](int woff, int Klen, int kbase) {
        const __nv_bfloat16* bh = WTh + woff;
        const __nv_bfloat16* bl = WTl + woff;
        int u = tid & 7;
        #pragma unroll
        for (int n = tid >> 3; n < 128; n += 32) {
            uint32_t sw = sw128((uint32_t)n * 128 + u * 16);
            cp_async16(sbase + SM_B + sw,          bh + (size_t)n * Klen + kbase + u * 8);
            cp_async16(sbase + SM_B + TILE_W + sw, bl + (size_t)n * Klen + kbase + u * 8);
        }
    };

    // A chunk (64 rows x 64k) into A3 slot: hi at A3+slot*T, lo at A3+(2+slot)*T
    auto fill_A = [&](int ch, int slot) {
        if (ch < 2) {
            uint8_t* aH = smem8 + SM_A3 + slot * TILE_A;
            uint8_t* aL = smem8 + SM_A3 + (2 + slot) * TILE_A;
            int c4 = tid & 15;
            #pragma unroll
            for (int r = tid >> 4; r < MT; r += 16) {
                int e = e0 + r;
                const float* src = hE + (size_t)e * HH + ch * 64;
                float4 v = *((const float4*)src + c4);
                uint32_t h01, l01, h23, l23;
                split2(v.x, v.y, h01, l01);
                split2(v.z, v.w, h23, l23);
                uint32_t sw = sw128((uint32_t)r * 128 + c4 * 8);
                *(uint2*)(aH + sw) = make_uint2(h01, h23);
                *(uint2*)(aL + sw) = make_uint2(l01, l23);
            }
        } else {
            uint32_t aH = sbase + SM_A3 + slot * TILE_A;
            uint32_t aL = sbase + SM_A3 + (2 + slot) * TILE_A;
            int u = tid & 7;
            #pragma unroll
            for (int r = tid >> 3; r < MT; r += 32) {
                int e = e0 + r;
                int b  = e / (KK * NN);
                int nb = load_nbidx(Eidx, is64, e);
                size_t off = ((size_t)b * NN + nb) * HH + (ch - 2) * 64 + u * 8;
                uint32_t sw = sw128((uint32_t)r * 128 + u * 16);
                cp_async16(aH + sw, vhi + off);
                cp_async16(aL + sw, vlo + off);
            }
        }
    };

    auto epi_act = [&](const float* __restrict__ bias, bool useCW, uint32_t dstOff) {
        #pragma unroll
        for (int mt = 0; mt < 2; mt++) {
            int row = m0 + mt * 16 + (lane >> 2);
            const float* cw0 = nullptr; const float* cw1 = nullptr;
            if (useCW) {
                cw0 = g_cw + (size_t)((e0 + row) / KK) * HH;
                cw1 = g_cw + (size_t)((e0 + row + 8) / KK) * HH;
            }
            #pragma unroll
            for (int nt = 0; nt < 4; nt++) {
                int c0 = n0 + nt * 8 + 2 * (lane & 3);
                float b00, b01, b10, b11;
                if (useCW) { b00 = cw0[c0]; b01 = cw0[c0 + 1]; b10 = cw1[c0]; b11 = cw1[c0 + 1]; }
                else       { b00 = b10 = bias[c0]; b01 = b11 = bias[c0 + 1]; }
                int kt = c0 >> 6, kk = c0 & 63;
                uint8_t* dH = smem8 + dstOff + kt * TILE_A;
                uint8_t* dL = smem8 + dstOff + (2 + kt) * TILE_A;
                float x0 = gelu_exact(acc[mt][nt][0] + b00);
                float y0 = gelu_exact(acc[mt][nt][1] + b01);
                float x1 = gelu_exact(acc[mt][nt][2] + b10);
                float y1 = gelu_exact(acc[mt][nt][3] + b11);
                uint32_t hi, lo;
                split2(x0, y0, hi, lo);
                uint32_t sw = sw128((uint32_t)(row * 128 + kk * 2));
                *(uint32_t*)(dH + sw) = hi; *(uint32_t*)(dL + sw) = lo;
                split2(x1, y1, hi, lo);
                sw = sw128((uint32_t)((row + 8) * 128 + kk * 2));
                *(uint32_t*)(dH + sw) = hi; *(uint32_t*)(dL + sw) = lo;
            }
        }
    };

    const uint32_t bHi = sbase + SM_B;
    const uint32_t bLo = sbase + SM_B + TILE_W;

    // ===== GEMM1: K=256 (hE + nbr), 4 chunks; A double-buffered, B single-buffered =====
    zero_acc();
    fill_B(WOFF_G1, 384, 128);
    fill_A(0, 0);
    CP_WAIT_ALL();
    __syncthreads();
    #pragma unroll 1
    for (int ch = 0; ch < 4; ch++) {
        int bi = ch & 1;
        if (ch < 3) fill_A(ch + 1, bi ^ 1);
        mma_chunk(sbase + SM_A3 + bi * TILE_A,
                  sbase + SM_A3 + (2 + bi) * TILE_A,
                  bHi, bLo, m0, n0, lane, acc);
        __syncthreads();                   // all warps done reading B
        if (ch < 3) {
            fill_B(WOFF_G1, 384, 128 + (ch + 1) * 64);
            CP_WAIT_ALL();                 // covers fill_A too
            __syncthreads();
        }
    }

    // ===== epilogue1 (+cw) -> A2; refill B for GEMM2 k0 =====
    epi_act(nullptr, true, SM_A2);
    fill_B(WOFF_G2, 128, 0);
    zero_acc();
    CP_WAIT_ALL();
    __syncthreads();

    // ===== GEMM2 =====
    mma_chunk(sbase + SM_A2, sbase + SM_A2 + 2 * TILE_A, bHi, bLo, m0, n0, lane, acc);
    __syncthreads();
    fill_B(WOFF_G2, 128, 64);
    CP_WAIT_ALL();
    __syncthreads();
    mma_chunk(sbase + SM_A2 + TILE_A, sbase + SM_A2 + 3 * TILE_A, bHi, bLo, m0, n0, lane, acc);
    __syncthreads();

    // ===== epilogue2 -> A3; refill B for GEMM3 k0 =====
    epi_act(bb, false, SM_A3);
    fill_B(WOFF_G3, 128, 0);
    zero_acc();
    CP_WAIT_ALL();
    __syncthreads();

    // ===== GEMM3 =====
    mma_chunk(sbase + SM_A3, sbase + SM_A3 + 2 * TILE_A, bHi, bLo, m0, n0, lane, acc);
    __syncthreads();
    fill_B(WOFF_G3, 128, 64);
    CP_WAIT_ALL();
    __syncthreads();
    mma_chunk(sbase + SM_A3 + TILE_A, sbase + SM_A3 + 3 * TILE_A, bHi, bLo, m0, n0, lane, acc);
    __syncthreads();   // B region dead -> fp32 staging (64x128 f32 = 32KB)

    float* sOut = (float*)(smem8 + SM_B);
    {
        #pragma unroll
        for (int mt = 0; mt < 2; mt++) {
            int row = m0 + mt * 16 + (lane >> 2);
            float mk0 = 1.f, mk1 = 1.f;
            if (!EDGE) { mk0 = maskA[e0 + row]; mk1 = maskA[e0 + row + 8]; }
            #pragma unroll
            for (int nt = 0; nt < 4; nt++) {
                int c0 = n0 + nt * 8 + 2 * (lane & 3);
                float b0v = bc[c0], b1v = bc[c0 + 1];
                sOut[row * 128 + c0]           = (acc[mt][nt][0] + b0v) * mk0;
                sOut[row * 128 + c0 + 1]       = (acc[mt][nt][1] + b1v) * mk0;
                sOut[(row + 8) * 128 + c0]     = (acc[mt][nt][2] + b0v) * mk1;
                sOut[(row + 8) * 128 + c0 + 1] = (acc[mt][nt][3] + b1v) * mk1;
            }
        }
        __syncthreads();
    }

    if (!EDGE) {
        float4* d4 = (float4*)(g_m + (size_t)e0 * HH);
        const float4* s4 = (const float4*)sOut;
        #pragma unroll
        for (int p = 0; p < 8; p++) d4[tid + p * NTHR] = s4[tid + p * NTHR];
    } else {
        for (int r = wid; r < MT; r += 8) {
            const float* her = hE + (size_t)(e0 + r) * HH;
            float v[4];
            #pragma unroll
            for (int u = 0; u < 4; u++) {
                int c = lane + 32 * u;
                v[u] = sOut[r * 128 + c] + her[c];
            }
            float s  = v[0] + v[1] + v[2] + v[3];
            float ss = v[0]*v[0] + v[1]*v[1] + v[2]*v[2] + v[3]*v[3];
            #pragma unroll
            for (int o = 16; o; o >>= 1) {
                s  += __shfl_xor_sync(0xffffffffu, s, o);
                ss += __shfl_xor_sync(0xffffffffu, ss, o);
            }
            float mean = s * (1.0f / 128.0f);
            float rstd = rsqrtf(ss * (1.0f / 128.0f) - mean * mean + 1e-5f);
            #pragma unroll
            for (int u = 0; u < 4; u++) {
                int c = lane + 32 * u;
                out[(size_t)(e0 + r) * HH + c] = (v[u] - mean) * rstd * lng[c] + lnb[c];
            }
        }
    }
}

// ---------------- node reduction + LN1 ----------------
__global__ void __launch_bounds__(128)
reduce_ln1(const float* __restrict__ hV,
           const float* __restrict__ lng, const float* __restrict__ lnb)
{
    int bn = blockIdx.x, j = threadIdx.x;
    int w = j >> 5, lane = j & 31;
    float s = 0.f;
    const float* mp = g_m + (size_t)bn * KK * HH + j;
    #pragma unroll 8
    for (int k = 0; k < KK; k++) s += mp[(size_t)k * HH];
    float v = hV[(size_t)bn * HH + j] + s * (1.0f / 48.0f);

    __shared__ float rs[4], rq[4];
    float a = v, q = v * v;
    #pragma unroll
    for (int o = 16; o; o >>= 1) {
        a += __shfl_xor_sync(0xffffffffu, a, o);
        q += __shfl_xor_sync(0xffffffffu, q, o);
    }
    if (lane == 0) { rs[w] = a; rq[w] = q; }
    __syncthreads();
    float S = rs[0] + rs[1] + rs[2] + rs[3];
    float Q = rq[0] + rq[1] + rq[2] + rq[3];
    float mean = S * (1.0f / 128.0f);
    float rstd = rsqrtf(Q * (1.0f / 128.0f) - mean * mean + 1e-5f);
    g_hV1[(size_t)bn * HH + j] = (v - mean) * rstd * lng[j] + lnb[j];
}

// ---------------- FFN + LN2 + mask_V (+ bf16 split of h_Vn) ----------------
__global__ void __launch_bounds__(256, 1)
ffn_kernel(const float* __restrict__ Win, const float* __restrict__ bin,
           const float* __restrict__ Wout, const float* __restrict__ bout,
           const float* __restrict__ lng, const float* __restrict__ lnb,
           const float* __restrict__ maskV,
           float* __restrict__ out)
{
    __shared__ float sX[16 * 128];
    __shared__ float sH[16 * 512];
    const int tid  = threadIdx.x;
    const int row0 = blockIdx.x * 16;

    for (int idx = tid; idx < 16 * 128; idx += 256)
        sX[idx] = g_hV1[(size_t)row0 * 128 + idx];
    __syncthreads();

    {
        const int j0 = tid * 2;
        float acc[16][2];
        #pragma unroll
        for (int r = 0; r < 16; r++) { acc[r][0] = bin[j0]; acc[r][1] = bin[j0 + 1]; }
        #pragma unroll 2
        for (int i = 0; i < 128; i++) {
            float2 w = *reinterpret_cast<const float2*>(Win + i * FFD + j0);
            #pragma unroll
            for (int r = 0; r < 16; r++) {
                float a = sX[r * 128 + i];
                acc[r][0] = fmaf(a, w.x, acc[r][0]);
                acc[r][1] = fmaf(a, w.y, acc[r][1]);
            }
        }
        #pragma unroll
        for (int r = 0; r < 16; r++) {
            sH[r * FFD + j0]     = gelu_exact(acc[r][0]);
            sH[r * FFD + j0 + 1] = gelu_exact(acc[r][1]);
        }
    }
    __syncthreads();

    {
        const int j = tid & 127, rh = tid >> 7;
        float acc[8];
        #pragma unroll
        for (int r = 0; r < 8; r++) acc[r] = bout[j];
        #pragma unroll 2
        for (int i = 0; i < FFD; i++) {
            float w = Wout[i * 128 + j];
            #pragma unroll
            for (int r = 0; r < 8; r++)
                acc[r] = fmaf(sH[(rh * 8 + r) * FFD + i], w, acc[r]);
        }
        #pragma unroll
        for (int r = 0; r < 8; r++)
            sX[(rh * 8 + r) * 128 + j] += acc[r];
    }
    __syncthreads();

    int w = tid >> 5, lane = tid & 31;
    for (int r = w; r < 16; r += 8) {
        float v[4];
        #pragma unroll
        for (int u = 0; u < 4; u++) v[u] = sX[r * 128 + lane + 32 * u];
        float s  = v[0] + v[1] + v[2] + v[3];
        float ss = v[0]*v[0] + v[1]*v[1] + v[2]*v[2] + v[3]*v[3];
        #pragma unroll
        for (int o = 16; o; o >>= 1) {
            s  += __shfl_xor_sync(0xffffffffu, s, o);
            ss += __shfl_xor_sync(0xffffffffu, ss, o);
        }
        float mean = s * (1.0f / 128.0f);
        float rstd = rsqrtf(ss * (1.0f / 128.0f) - mean * mean + 1e-5f);
        float mk = maskV[row0 + r];
        #pragma unroll
        for (int u = 0; u < 4; u++) {
            int c = lane + 32 * u;
            float val = mk * ((v[u] - mean) * rstd * lng[c] + lnb[c]);
            size_t gi = ((size_t)row0 + r) * 128 + c;
            out[gi] = val;
            __nv_bfloat16 h = __float2bfloat16(val);
            g_hV2hi[gi] = h;
            g_hV2lo[gi] = __float2bfloat16(val - __bfloat162float(h));
        }
    }
}

extern "C" void kernel_launch(void* const* d_in, const int* in_sizes, int n_in,
                              void* d_out, int out_size)
{
    const float* hV    = (const float*)d_in[0];
    const float* hE    = (const float*)d_in[1];
    const void*  Eidx  = d_in[2];
    const float* maskV = (const float*)d_in[3];
    const float* maskA = (const float*)d_in[4];
    const float* W1w  = (const float*)d_in[5],  *W1b  = (const float*)d_in[6];
    const float* W2w  = (const float*)d_in[7],  *W2b  = (const float*)d_in[8];
    const float* W3w  = (const float*)d_in[9],  *W3b  = (const float*)d_in[10];
    const float* W11w = (const float*)d_in[11], *W11b = (const float*)d_in[12];
    const float* W12w = (const float*)d_in[13], *W12b = (const float*)d_in[14];
    const float* W13w = (const float*)d_in[15], *W13b = (const float*)d_in[16];
    const float* Winw = (const float*)d_in[17], *Winb = (const float*)d_in[18];
    const float* Woutw= (const float*)d_in[19], *Woutb= (const float*)d_in[20];
    const float* ln1g = (const float*)d_in[21], *ln1b = (const float*)d_in[22];
    const float* ln2g = (const float*)d_in[23], *ln2b = (const float*)d_in[24];
    const float* ln3g = (const float*)d_in[25], *ln3b = (const float*)d_in[26];

    float* out_hV = (float*)d_out;
    float* out_hE = out_hV + (size_t)BN * HH;

    cudaFuncSetAttribute(gemm_msg_kernel<false>, cudaFuncAttributeMaxDynamicSharedMemorySize, SM_TOTAL);
    cudaFuncSetAttribute(gemm_msg_kernel<true>,  cudaFuncAttributeMaxDynamicSharedMemorySize, SM_TOTAL);

    __nv_bfloat16 *vhi, *vlo, *v2hi, *v2lo;
    cudaGetSymbolAddress((void**)&vhi,  g_hVhi);
    cudaGetSymbolAddress((void**)&vlo,  g_hVlo);
    cudaGetSymbolAddress((void**)&v2hi, g_hV2hi);
    cudaGetSymbolAddress((void**)&v2lo, g_hV2lo);

    detect_idx_kernel<<<1, 1>>>((const int*)Eidx);
    prep_all<<<PW_BLKS + PV_BLKS, 256>>>(W1w, W2w, W3w, W11w, W12w, W13w, hV);
    cw_kernel<<<BN, 128>>>(hV, W1w, W1b);
    gemm_msg_kernel<false><<<NCTA, NTHR, SM_TOTAL>>>(
        vhi, vlo, hE, Eidx, maskA, W2b, W3b, 0, nullptr, nullptr, nullptr);
    reduce_ln1<<<BN, 128>>>(hV, ln1g, ln1b);
    ffn_kernel<<<BN / 16, 256>>>(Winw, Winb, Woutw, Woutb, ln2g, ln2b, maskV, out_hV);
    cw_kernel<<<BN, 128>>>(out_hV, W11w, W11b);
    gemm_msg_kernel<true><<<NCTA, NTHR, SM_TOTAL>>>(
        v2hi, v2lo, hE, Eidx, maskA, W12b, W13b, WMSG, ln3g, ln3b, out_hE);

    (void)in_sizes; (void)n_in; (void)out_size;
}